// round 6
// baseline (speedup 1.0000x reference)
#include <cuda_runtime.h>
#include <math.h>

#define BATCH 1024
#define ED 128
#define MAXN 200
#define PAD_IDX 100000
#define LN_EPS 1e-5f
#define FULLM 0xffffffffu

__global__ __launch_bounds__(512, 2) void entity_encoder_kernel(
    const int*   __restrict__ entity,
    const int*   __restrict__ conn_left,
    const int*   __restrict__ conn_right,
    const float* __restrict__ emb,
    const float* __restrict__ W_bil,
    const float* __restrict__ W_tail,
    const float* __restrict__ W_head,
    const float* __restrict__ gamma,
    const float* __restrict__ beta,
    float*       __restrict__ out)
{
    const int b    = blockIdx.x;
    const int tid  = threadIdx.x;
    const int wid  = tid >> 5;
    const int lane = tid & 31;
    const int side = wid >> 3;
    const int sw   = wid & 7;

    __shared__ float s_wr[ED];
    __shared__ float s_head[2][ED];
    __shared__ float s_qp[512];
    __shared__ float s_q[ED];
    __shared__ float s_sc[2][MAXN];
    __shared__ int   s_conn[2][2 * MAXN];
    __shared__ float s_part[16][ED];
    __shared__ float s_zw[16];
    __shared__ float s_agg[2][ED];
    __shared__ float s_x[2][ED];
    __shared__ float s_redA[16];
    __shared__ float s_redB[16];
    __shared__ float s_stat[2][2];

    // ---- stage conn ids ----
    {
        const long base = (long)b * MAXN * 2;
        for (int i = tid; i < 2 * MAXN; i += 512) {
            s_conn[0][i] = conn_left[base + i];
            s_conn[1][i] = conn_right[base + i];
        }
    }

    // ---- head / weak_rel ----
    const int e0 = entity[b * 2 + 0];
    const int e1 = entity[b * 2 + 1];
    if (tid < ED) {
        float a = emb[(long)e0 * ED + tid];
        float c = emb[(long)e1 * ED + tid];
        s_wr[tid]      = c - a;
        s_head[0][tid] = a;
        s_head[1][tid] = c;
    }
    __syncthreads();

    // ---- q = wr @ W_bil (4-way d-split over 512 threads) ----
    {
        const int e  = tid & (ED - 1);
        const int qq = tid >> 7;
        const int d0 = qq * 32;
        float acc = 0.f;
        #pragma unroll 8
        for (int d = 0; d < 32; ++d)
            acc = fmaf(s_wr[d0 + d], W_bil[(d0 + d) * ED + e], acc);
        s_qp[tid] = acc;
    }
    __syncthreads();
    if (tid < ED)
        s_q[tid] = s_qp[tid] + s_qp[ED + tid] + s_qp[2 * ED + tid] + s_qp[3 * ED + tid];
    __syncthreads();

    // ---- scores: lane-split (4 neighbors / warp-iter, 3-shuffle reduce) ----
    {
        const int sub = lane >> 3;            // which neighbor in group
        const int seg = lane & 7;             // 16-dim segment
        float4 q4[4];
        #pragma unroll
        for (int k = 0; k < 4; ++k) q4[k] = ((const float4*)s_q)[seg * 4 + k];
        const int* cn = s_conn[side];
        float wmax = -INFINITY;

        #pragma unroll 1
        for (int g = 0; g < 6; g += 2) {
            const int m0 = 4 * (sw + 8 * g)       + sub;
            const int m1 = 4 * (sw + 8 * (g + 1)) + sub;
            const int rid0 = cn[2 * m0];
            const int rid1 = cn[2 * m1];
            const float4* row0 = (const float4*)(emb + (long)rid0 * ED + seg * 16);
            const float4* row1 = (const float4*)(emb + (long)rid1 * ED + seg * 16);
            float4 r0[4], r1[4];
            #pragma unroll
            for (int k = 0; k < 4; ++k) r0[k] = row0[k];
            #pragma unroll
            for (int k = 0; k < 4; ++k) r1[k] = row1[k];
            float v0 = 0.f, v1 = 0.f;
            #pragma unroll
            for (int k = 0; k < 4; ++k) {
                v0 += q4[k].x * r0[k].x + q4[k].y * r0[k].y + q4[k].z * r0[k].z + q4[k].w * r0[k].w;
                v1 += q4[k].x * r1[k].x + q4[k].y * r1[k].y + q4[k].z * r1[k].z + q4[k].w * r1[k].w;
            }
            v0 += __shfl_xor_sync(FULLM, v0, 1);
            v1 += __shfl_xor_sync(FULLM, v1, 1);
            v0 += __shfl_xor_sync(FULLM, v0, 2);
            v1 += __shfl_xor_sync(FULLM, v1, 2);
            v0 += __shfl_xor_sync(FULLM, v0, 4);
            v1 += __shfl_xor_sync(FULLM, v1, 4);
            if (rid0 == PAD_IDX) v0 = -INFINITY;
            if (rid1 == PAD_IDX) v1 = -INFINITY;
            wmax = fmaxf(wmax, fmaxf(v0, v1));
            if (seg == 0) {
                s_sc[side][m0] = v0;
                s_sc[side][m1] = v1;
            }
        }
        // tail m = 192 + sw (full-warp dot)
        {
            const int m   = 192 + sw;
            const int rid = cn[2 * m];
            float4 qq = ((const float4*)s_q)[lane];
            float4 r  = ((const float4*)(emb + (long)rid * ED))[lane];
            float v = qq.x * r.x + qq.y * r.y + qq.z * r.z + qq.w * r.w;
            v += __shfl_xor_sync(FULLM, v, 16);
            v += __shfl_xor_sync(FULLM, v, 8);
            v += __shfl_xor_sync(FULLM, v, 4);
            v += __shfl_xor_sync(FULLM, v, 2);
            v += __shfl_xor_sync(FULLM, v, 1);
            if (rid == PAD_IDX) v = -INFINITY;
            wmax = fmaxf(wmax, v);
            if (lane == 0) s_sc[side][m] = v;
        }
        // warp max
        wmax = fmaxf(wmax, __shfl_xor_sync(FULLM, wmax, 16));
        wmax = fmaxf(wmax, __shfl_xor_sync(FULLM, wmax, 8));
        wmax = fmaxf(wmax, __shfl_xor_sync(FULLM, wmax, 4));
        wmax = fmaxf(wmax, __shfl_xor_sync(FULLM, wmax, 2));
        wmax = fmaxf(wmax, __shfl_xor_sync(FULLM, wmax, 1));
        if (lane == 0) s_redA[wid] = wmax;
    }
    __syncthreads();

    // ---- block max (per side), no extra barrier ----
    float gmax;
    {
        float m2 = -INFINITY;
        #pragma unroll
        for (int w = 0; w < 8; ++w) m2 = fmaxf(m2, s_redA[side * 8 + w]);
        gmax = m2;
    }

    // ---- agg with UNNORMALIZED weights e = exp(s - gmax); Z alongside ----
    {
        const int*   cn = s_conn[side];
        const float* sc = s_sc[side];
        float4 acc = make_float4(0.f, 0.f, 0.f, 0.f);
        float  z   = 0.f;
        #pragma unroll 1
        for (int g = 0; g < 6; ++g) {
            const int mb = sw + 32 * g;
            int eid[4];
            float e[4];
            #pragma unroll
            for (int i = 0; i < 4; ++i) {
                const int m = mb + 8 * i;
                eid[i] = cn[2 * m + 1];
                e[i]   = __expf(sc[m] - gmax);
            }
            float4 t[4];
            #pragma unroll
            for (int i = 0; i < 4; ++i)
                t[i] = ((const float4*)(emb + (long)eid[i] * ED))[lane];
            #pragma unroll
            for (int i = 0; i < 4; ++i) {
                acc.x = fmaf(e[i], t[i].x, acc.x);
                acc.y = fmaf(e[i], t[i].y, acc.y);
                acc.z = fmaf(e[i], t[i].z, acc.z);
                acc.w = fmaf(e[i], t[i].w, acc.w);
                z    += e[i];
            }
        }
        {   // tail
            const int m   = sw + 192;
            const int eid = cn[2 * m + 1];
            const float e = __expf(sc[m] - gmax);
            float4 t = ((const float4*)(emb + (long)eid * ED))[lane];
            acc.x = fmaf(e, t.x, acc.x);
            acc.y = fmaf(e, t.y, acc.y);
            acc.z = fmaf(e, t.z, acc.z);
            acc.w = fmaf(e, t.w, acc.w);
            z    += e;
        }
        ((float4*)s_part[wid])[lane] = acc;
        if (lane == 0) s_zw[wid] = z;
    }
    __syncthreads();
    if (tid < 256) {
        const int sR = tid >> 7;
        const int t  = tid & (ED - 1);
        float s = 0.f;
        #pragma unroll
        for (int w = 0; w < 8; ++w) s += s_part[sR * 8 + w][t];
        float Z = 0.f;
        #pragma unroll
        for (int w = 0; w < 8; ++w) Z += s_zw[sR * 8 + w];
        s_agg[sR][t] = s * (1.f / Z);
    }
    __syncthreads();

    // ---- h = relu(agg.W_tail^T + head.W_head^T) for BOTH sides ----
    {
        const float4 aL = ((const float4*)s_agg[0])[lane];
        const float4 hL = ((const float4*)s_head[0])[lane];
        const float4 aR = ((const float4*)s_agg[1])[lane];
        const float4 hR = ((const float4*)s_head[1])[lane];
        #pragma unroll 1
        for (int i0 = wid; i0 < ED; i0 += 32) {
            const int i1 = i0 + 16;
            float4 wt0 = ((const float4*)(W_tail + i0 * ED))[lane];
            float4 wh0 = ((const float4*)(W_head + i0 * ED))[lane];
            float4 wt1 = ((const float4*)(W_tail + i1 * ED))[lane];
            float4 wh1 = ((const float4*)(W_head + i1 * ED))[lane];
            float vL0 = aL.x * wt0.x + aL.y * wt0.y + aL.z * wt0.z + aL.w * wt0.w
                      + hL.x * wh0.x + hL.y * wh0.y + hL.z * wh0.z + hL.w * wh0.w;
            float vR0 = aR.x * wt0.x + aR.y * wt0.y + aR.z * wt0.z + aR.w * wt0.w
                      + hR.x * wh0.x + hR.y * wh0.y + hR.z * wh0.z + hR.w * wh0.w;
            float vL1 = aL.x * wt1.x + aL.y * wt1.y + aL.z * wt1.z + aL.w * wt1.w
                      + hL.x * wh1.x + hL.y * wh1.y + hL.z * wh1.z + hL.w * wh1.w;
            float vR1 = aR.x * wt1.x + aR.y * wt1.y + aR.z * wt1.z + aR.w * wt1.w
                      + hR.x * wh1.x + hR.y * wh1.y + hR.z * wh1.z + hR.w * wh1.w;
            #pragma unroll
            for (int d = 16; d >= 1; d >>= 1) {
                vL0 += __shfl_xor_sync(FULLM, vL0, d);
                vR0 += __shfl_xor_sync(FULLM, vR0, d);
                vL1 += __shfl_xor_sync(FULLM, vL1, d);
                vR1 += __shfl_xor_sync(FULLM, vR1, d);
            }
            if (lane == 0) {
                s_x[0][i0] = fmaxf(vL0, 0.f) + s_head[0][i0];
                s_x[1][i0] = fmaxf(vR0, 0.f) + s_head[1][i0];
                s_x[0][i1] = fmaxf(vL1, 0.f) + s_head[0][i1];
                s_x[1][i1] = fmaxf(vR1, 0.f) + s_head[1][i1];
            }
        }
    }
    __syncthreads();

    // ---- two LayerNorms in parallel ----
    if (tid < 256) {
        const int sL = tid >> 7;
        const int t  = tid & (ED - 1);
        const int w4 = t >> 5;
        float xv = s_x[sL][t];
        float s1 = xv, s2 = xv * xv;
        #pragma unroll
        for (int d = 16; d >= 1; d >>= 1) {
            s1 += __shfl_xor_sync(FULLM, s1, d);
            s2 += __shfl_xor_sync(FULLM, s2, d);
        }
        if (lane == 0) { s_redA[sL * 8 + w4] = s1; s_redB[sL * 8 + w4] = s2; }
    }
    __syncthreads();
    if (tid < 256) {
        const int sL = tid >> 7;
        const int t  = tid & (ED - 1);
        if (t == 0) {
            float t1 = 0.f, t2 = 0.f;
            #pragma unroll
            for (int w = 0; w < 4; ++w) { t1 += s_redA[sL * 8 + w]; t2 += s_redB[sL * 8 + w]; }
            float mu  = t1 * (1.f / ED);
            float var = t2 * (1.f / ED) - mu * mu;
            s_stat[sL][0] = mu;
            s_stat[sL][1] = rsqrtf(var + LN_EPS);
        }
    }
    __syncthreads();
    if (tid < 256) {
        const int sL = tid >> 7;
        const int t  = tid & (ED - 1);
        float mu = s_stat[sL][0], rstd = s_stat[sL][1];
        float o = (s_x[sL][t] - mu) * rstd * gamma[t] + beta[t];
        out[((long)sL * BATCH + b) * ED + t] = o;
    }
}

extern "C" void kernel_launch(void* const* d_in, const int* in_sizes, int n_in,
                              void* d_out, int out_size) {
    (void)in_sizes; (void)n_in; (void)out_size;
    const int*   entity     = (const int*)  d_in[0];
    const int*   conn_left  = (const int*)  d_in[1];
    const int*   conn_right = (const int*)  d_in[2];
    const float* emb        = (const float*)d_in[3];
    const float* W_bil      = (const float*)d_in[4];
    const float* W_tail     = (const float*)d_in[5];
    const float* W_head     = (const float*)d_in[6];
    const float* gamma      = (const float*)d_in[7];
    const float* beta       = (const float*)d_in[8];
    float* out = (float*)d_out;

    entity_encoder_kernel<<<BATCH, 512>>>(entity, conn_left, conn_right, emb,
                                          W_bil, W_tail, W_head, gamma, beta, out);
}

// round 8
// speedup vs baseline: 1.2142x; 1.2142x over previous
#include <cuda_runtime.h>
#include <math.h>

#define BATCH 1024
#define ED 128
#define MAXN 200
#define PAD_IDX 100000
#define LN_EPS 1e-5f
#define FULLM 0xffffffffu

__global__ __launch_bounds__(512, 2) void entity_encoder_kernel(
    const int*   __restrict__ entity,
    const int*   __restrict__ conn_left,
    const int*   __restrict__ conn_right,
    const float* __restrict__ emb,
    const float* __restrict__ W_bil,
    const float* __restrict__ W_tail,
    const float* __restrict__ W_head,
    const float* __restrict__ gamma,
    const float* __restrict__ beta,
    float*       __restrict__ out)
{
    const int b    = blockIdx.x;
    const int tid  = threadIdx.x;
    const int wid  = tid >> 5;
    const int lane = tid & 31;
    const int side = wid >> 3;      // 0 = left, 1 = right
    const int sw   = wid & 7;       // warp within side

    __shared__ float s_wr[ED];
    __shared__ float s_head[2][ED];
    __shared__ float s_qp[512];
    __shared__ float s_q[ED];
    __shared__ float s_sc[2][MAXN];
    __shared__ int   s_conn[2][2 * MAXN];
    __shared__ float s_part[16][ED];
    __shared__ float s_zw[16];
    __shared__ float s_agg[2][ED];
    __shared__ float s_x[2][ED];
    __shared__ float s_redA[16];
    __shared__ float s_redB[16];
    __shared__ float s_stat[2][2];

    // ---- stage conn ids (coalesced, both sides) ----
    {
        const long base = (long)b * MAXN * 2;
        for (int i = tid; i < 2 * MAXN; i += 512) {
            s_conn[0][i] = conn_left[base + i];
            s_conn[1][i] = conn_right[base + i];
        }
    }

    // ---- head / weak_rel ----
    const int e0 = entity[b * 2 + 0];
    const int e1 = entity[b * 2 + 1];
    if (tid < ED) {
        float a = emb[(long)e0 * ED + tid];
        float c = emb[(long)e1 * ED + tid];
        s_wr[tid]      = c - a;
        s_head[0][tid] = a;
        s_head[1][tid] = c;
    }
    __syncthreads();

    // ---- q[e] = sum_d wr[d] * W_bil[d, e]  (4-way d-split over 512 thr) ----
    {
        const int e  = tid & (ED - 1);
        const int qq = tid >> 7;
        const int d0 = qq * 32;
        float acc = 0.f;
        #pragma unroll 8
        for (int d = 0; d < 32; ++d)
            acc = fmaf(s_wr[d0 + d], W_bil[(d0 + d) * ED + e], acc);
        s_qp[tid] = acc;
    }
    __syncthreads();
    if (tid < ED)
        s_q[tid] = s_qp[tid] + s_qp[ED + tid] + s_qp[2 * ED + tid] + s_qp[3 * ED + tid];
    __syncthreads();

    // ---- scores: warp per neighbor, 4 gathers in flight; track warp max ----
    {
        const float4 q4 = ((const float4*)s_q)[lane];
        const int*   cn = s_conn[side];
        float wmax = -INFINITY;
        #pragma unroll 1
        for (int g = 0; g < 6; ++g) {
            const int mb = sw + 32 * g;
            int rid[4];
            #pragma unroll
            for (int i = 0; i < 4; ++i) rid[i] = cn[2 * (mb + 8 * i)];
            float4 r[4];
            #pragma unroll
            for (int i = 0; i < 4; ++i)
                r[i] = ((const float4*)(emb + (long)rid[i] * ED))[lane];
            #pragma unroll
            for (int i = 0; i < 4; ++i) {
                float v = q4.x * r[i].x + q4.y * r[i].y + q4.z * r[i].z + q4.w * r[i].w;
                v += __shfl_xor_sync(FULLM, v, 16);
                v += __shfl_xor_sync(FULLM, v, 8);
                v += __shfl_xor_sync(FULLM, v, 4);
                v += __shfl_xor_sync(FULLM, v, 2);
                v += __shfl_xor_sync(FULLM, v, 1);
                if (rid[i] == PAD_IDX) v = -INFINITY;
                wmax = fmaxf(wmax, v);
                if (lane == 0) s_sc[side][mb + 8 * i] = v;
            }
        }
        {   // tail m = sw + 192
            const int m   = sw + 192;
            const int rid = cn[2 * m];
            float4 r = ((const float4*)(emb + (long)rid * ED))[lane];
            float v = q4.x * r.x + q4.y * r.y + q4.z * r.z + q4.w * r.w;
            v += __shfl_xor_sync(FULLM, v, 16);
            v += __shfl_xor_sync(FULLM, v, 8);
            v += __shfl_xor_sync(FULLM, v, 4);
            v += __shfl_xor_sync(FULLM, v, 2);
            v += __shfl_xor_sync(FULLM, v, 1);
            if (rid == PAD_IDX) v = -INFINITY;
            wmax = fmaxf(wmax, v);
            if (lane == 0) s_sc[side][m] = v;
        }
        // wmax is already uniform across the warp (every lane saw every v)
        if (lane == 0) s_redA[wid] = wmax;
    }
    __syncthreads();

    // ---- per-side block max (register, no extra barrier) ----
    float gmax;
    {
        float m2 = -INFINITY;
        #pragma unroll
        for (int w = 0; w < 8; ++w) m2 = fmaxf(m2, s_redA[side * 8 + w]);
        gmax = m2;
    }

    // ---- agg with UNNORMALIZED weights e = exp(s - gmax); Z alongside ----
    {
        const int*   cn = s_conn[side];
        const float* sc = s_sc[side];
        float4 acc = make_float4(0.f, 0.f, 0.f, 0.f);
        float  z   = 0.f;
        #pragma unroll 1
        for (int g = 0; g < 6; ++g) {
            const int mb = sw + 32 * g;
            int eid[4];
            float e[4];
            #pragma unroll
            for (int i = 0; i < 4; ++i) {
                const int m = mb + 8 * i;
                eid[i] = cn[2 * m + 1];
                e[i]   = __expf(sc[m] - gmax);
            }
            float4 t[4];
            #pragma unroll
            for (int i = 0; i < 4; ++i)
                t[i] = ((const float4*)(emb + (long)eid[i] * ED))[lane];
            #pragma unroll
            for (int i = 0; i < 4; ++i) {
                acc.x = fmaf(e[i], t[i].x, acc.x);
                acc.y = fmaf(e[i], t[i].y, acc.y);
                acc.z = fmaf(e[i], t[i].z, acc.z);
                acc.w = fmaf(e[i], t[i].w, acc.w);
                z    += e[i];
            }
        }
        {   // tail
            const int m   = sw + 192;
            const int eid = cn[2 * m + 1];
            const float e = __expf(sc[m] - gmax);
            float4 t = ((const float4*)(emb + (long)eid * ED))[lane];
            acc.x = fmaf(e, t.x, acc.x);
            acc.y = fmaf(e, t.y, acc.y);
            acc.z = fmaf(e, t.z, acc.z);
            acc.w = fmaf(e, t.w, acc.w);
            z    += e;
        }
        ((float4*)s_part[wid])[lane] = acc;
        if (lane == 0) s_zw[wid] = z;
    }
    __syncthreads();
    if (tid < 256) {
        const int sR = tid >> 7;
        const int t  = tid & (ED - 1);
        float s = 0.f;
        #pragma unroll
        for (int w = 0; w < 8; ++w) s += s_part[sR * 8 + w][t];
        float Z = 0.f;
        #pragma unroll
        for (int w = 0; w < 8; ++w) Z += s_zw[sR * 8 + w];
        s_agg[sR][t] = s * (1.f / Z);
    }
    __syncthreads();

    // ---- h = relu(agg.W_tail^T + head.W_head^T) for BOTH sides ----
    {
        const float4 aL = ((const float4*)s_agg[0])[lane];
        const float4 hL = ((const float4*)s_head[0])[lane];
        const float4 aR = ((const float4*)s_agg[1])[lane];
        const float4 hR = ((const float4*)s_head[1])[lane];
        #pragma unroll 1
        for (int i0 = wid; i0 < ED; i0 += 32) {
            const int i1 = i0 + 16;
            float4 wt0 = ((const float4*)(W_tail + i0 * ED))[lane];
            float4 wh0 = ((const float4*)(W_head + i0 * ED))[lane];
            float4 wt1 = ((const float4*)(W_tail + i1 * ED))[lane];
            float4 wh1 = ((const float4*)(W_head + i1 * ED))[lane];
            float vL0 = aL.x * wt0.x + aL.y * wt0.y + aL.z * wt0.z + aL.w * wt0.w
                      + hL.x * wh0.x + hL.y * wh0.y + hL.z * wh0.z + hL.w * wh0.w;
            float vR0 = aR.x * wt0.x + aR.y * wt0.y + aR.z * wt0.z + aR.w * wt0.w
                      + hR.x * wh0.x + hR.y * wh0.y + hR.z * wh0.z + hR.w * wh0.w;
            float vL1 = aL.x * wt1.x + aL.y * wt1.y + aL.z * wt1.z + aL.w * wt1.w
                      + hL.x * wh1.x + hL.y * wh1.y + hL.z * wh1.z + hL.w * wh1.w;
            float vR1 = aR.x * wt1.x + aR.y * wt1.y + aR.z * wt1.z + aR.w * wt1.w
                      + hR.x * wh1.x + hR.y * wh1.y + hR.z * wh1.z + hR.w * wh1.w;
            #pragma unroll
            for (int d = 16; d >= 1; d >>= 1) {
                vL0 += __shfl_xor_sync(FULLM, vL0, d);
                vR0 += __shfl_xor_sync(FULLM, vR0, d);
                vL1 += __shfl_xor_sync(FULLM, vL1, d);
                vR1 += __shfl_xor_sync(FULLM, vR1, d);
            }
            if (lane == 0) {
                s_x[0][i0] = fmaxf(vL0, 0.f) + s_head[0][i0];
                s_x[1][i0] = fmaxf(vR0, 0.f) + s_head[1][i0];
                s_x[0][i1] = fmaxf(vL1, 0.f) + s_head[0][i1];
                s_x[1][i1] = fmaxf(vR1, 0.f) + s_head[1][i1];
            }
        }
    }
    __syncthreads();

    // ---- two LayerNorms in parallel ----
    if (tid < 256) {
        const int sL = tid >> 7;
        const int t  = tid & (ED - 1);
        const int w4 = t >> 5;
        float xv = s_x[sL][t];
        float s1 = xv, s2 = xv * xv;
        #pragma unroll
        for (int d = 16; d >= 1; d >>= 1) {
            s1 += __shfl_xor_sync(FULLM, s1, d);
            s2 += __shfl_xor_sync(FULLM, s2, d);
        }
        if (lane == 0) { s_redA[sL * 8 + w4] = s1; s_redB[sL * 8 + w4] = s2; }
    }
    __syncthreads();
    if (tid < 256) {
        const int sL = tid >> 7;
        const int t  = tid & (ED - 1);
        if (t == 0) {
            float t1 = 0.f, t2 = 0.f;
            #pragma unroll
            for (int w = 0; w < 4; ++w) { t1 += s_redA[sL * 8 + w]; t2 += s_redB[sL * 8 + w]; }
            float mu  = t1 * (1.f / ED);
            float var = t2 * (1.f / ED) - mu * mu;
            s_stat[sL][0] = mu;
            s_stat[sL][1] = rsqrtf(var + LN_EPS);
        }
    }
    __syncthreads();
    if (tid < 256) {
        const int sL = tid >> 7;
        const int t  = tid & (ED - 1);
        float mu = s_stat[sL][0], rstd = s_stat[sL][1];
        float o = (s_x[sL][t] - mu) * rstd * gamma[t] + beta[t];
        out[((long)sL * BATCH + b) * ED + t] = o;
    }
}

extern "C" void kernel_launch(void* const* d_in, const int* in_sizes, int n_in,
                              void* d_out, int out_size) {
    (void)in_sizes; (void)n_in; (void)out_size;
    const int*   entity     = (const int*)  d_in[0];
    const int*   conn_left  = (const int*)  d_in[1];
    const int*   conn_right = (const int*)  d_in[2];
    const float* emb        = (const float*)d_in[3];
    const float* W_bil      = (const float*)d_in[4];
    const float* W_tail     = (const float*)d_in[5];
    const float* W_head     = (const float*)d_in[6];
    const float* gamma      = (const float*)d_in[7];
    const float* beta       = (const float*)d_in[8];
    float* out = (float*)d_out;

    entity_encoder_kernel<<<BATCH, 512>>>(entity, conn_left, conn_right, emb,
                                          W_bil, W_tail, W_head, gamma, beta, out);
}

// round 9
// speedup vs baseline: 1.2595x; 1.0372x over previous
#include <cuda_runtime.h>
#include <math.h>
#include <float.h>

#define BATCH 1024
#define ED 128
#define MAXN 200
#define PAD_IDX 100000
#define LN_EPS 1e-5f
#define FULLM 0xffffffffu

__global__ __launch_bounds__(512, 2) void entity_encoder_kernel(
    const int*   __restrict__ entity,
    const int*   __restrict__ conn_left,
    const int*   __restrict__ conn_right,
    const float* __restrict__ emb,
    const float* __restrict__ W_bil,
    const float* __restrict__ W_tail,
    const float* __restrict__ W_head,
    const float* __restrict__ gamma,
    const float* __restrict__ beta,
    float*       __restrict__ out)
{
    const int b    = blockIdx.x;
    const int tid  = threadIdx.x;
    const int wid  = tid >> 5;
    const int lane = tid & 31;
    const int side = wid >> 3;      // 0 = left, 1 = right
    const int sw   = wid & 7;       // warp within side

    __shared__ float s_wr[ED];
    __shared__ float s_head[2][ED];
    __shared__ float s_qp[512];
    __shared__ float s_q[ED];
    __shared__ int2  s_conn[2][MAXN];     // (rel, ent) pairs
    __shared__ float s_part[16][ED];
    __shared__ float s_mw[16];
    __shared__ float s_zw[16];
    __shared__ float s_agg[2][ED];
    __shared__ float s_x[2][ED];
    __shared__ float s_redA[16];
    __shared__ float s_redB[16];
    __shared__ float s_stat[2][2];

    // ---- stage conn pairs (coalesced, both sides) ----
    {
        const int2* cl = (const int2*)(conn_left  + (long)b * MAXN * 2);
        const int2* cr = (const int2*)(conn_right + (long)b * MAXN * 2);
        for (int i = tid; i < MAXN; i += 512) {
            s_conn[0][i] = cl[i];
            s_conn[1][i] = cr[i];
        }
    }

    // ---- head / weak_rel ----
    const int e0 = entity[b * 2 + 0];
    const int e1 = entity[b * 2 + 1];
    if (tid < ED) {
        float a = emb[(long)e0 * ED + tid];
        float c = emb[(long)e1 * ED + tid];
        s_wr[tid]      = c - a;
        s_head[0][tid] = a;
        s_head[1][tid] = c;
    }
    __syncthreads();

    // ---- q[e] = sum_d wr[d] * W_bil[d, e]  (4-way d-split over 512 thr) ----
    {
        const int e  = tid & (ED - 1);
        const int qq = tid >> 7;
        const int d0 = qq * 32;
        float acc = 0.f;
        #pragma unroll 8
        for (int d = 0; d < 32; ++d)
            acc = fmaf(s_wr[d0 + d], W_bil[(d0 + d) * ED + e], acc);
        s_qp[tid] = acc;
    }
    __syncthreads();
    if (tid < ED)
        s_q[tid] = s_qp[tid] + s_qp[ED + tid] + s_qp[2 * ED + tid] + s_qp[3 * ED + tid];
    __syncthreads();

    // ---- SINGLE merged pass: score + online-softmax aggregate ----
    // warp handles neighbors m = sw + 8*j, j = 0..24
    {
        const float4 q4 = ((const float4*)s_q)[lane];
        const int2*  cn = s_conn[side];

        float  wm  = -FLT_MAX;                    // running max (uniform in warp)
        float  wz  = 0.f;                          // running Z
        float4 acc = make_float4(0.f, 0.f, 0.f, 0.f);

        #pragma unroll 1
        for (int g = 0; g < 6; ++g) {
            const int mb = sw + 32 * g;
            int2 c4[4];
            #pragma unroll
            for (int i = 0; i < 4; ++i) c4[i] = cn[mb + 8 * i];
            // issue all 8 row loads up front
            float4 r[4], t[4];
            #pragma unroll
            for (int i = 0; i < 4; ++i)
                r[i] = ((const float4*)(emb + (long)c4[i].x * ED))[lane];
            #pragma unroll
            for (int i = 0; i < 4; ++i)
                t[i] = ((const float4*)(emb + (long)c4[i].y * ED))[lane];
            #pragma unroll
            for (int i = 0; i < 4; ++i) {
                float v = q4.x * r[i].x + q4.y * r[i].y + q4.z * r[i].z + q4.w * r[i].w;
                v += __shfl_xor_sync(FULLM, v, 16);
                v += __shfl_xor_sync(FULLM, v, 8);
                v += __shfl_xor_sync(FULLM, v, 4);
                v += __shfl_xor_sync(FULLM, v, 2);
                v += __shfl_xor_sync(FULLM, v, 1);
                if (c4[i].x == PAD_IDX) v = -FLT_MAX;
                const float mn = fmaxf(wm, v);
                const float cc = __expf(wm - mn);   // rescale old state
                const float e  = __expf(v - mn);    // this neighbor's weight
                wm = mn;
                wz = wz * cc + e;
                acc.x = fmaf(acc.x, cc, e * t[i].x);
                acc.y = fmaf(acc.y, cc, e * t[i].y);
                acc.z = fmaf(acc.z, cc, e * t[i].z);
                acc.w = fmaf(acc.w, cc, e * t[i].w);
            }
        }
        {   // tail neighbor m = 192 + sw
            const int2 c1 = cn[192 + sw];
            float4 r = ((const float4*)(emb + (long)c1.x * ED))[lane];
            float4 t = ((const float4*)(emb + (long)c1.y * ED))[lane];
            float v = q4.x * r.x + q4.y * r.y + q4.z * r.z + q4.w * r.w;
            v += __shfl_xor_sync(FULLM, v, 16);
            v += __shfl_xor_sync(FULLM, v, 8);
            v += __shfl_xor_sync(FULLM, v, 4);
            v += __shfl_xor_sync(FULLM, v, 2);
            v += __shfl_xor_sync(FULLM, v, 1);
            if (c1.x == PAD_IDX) v = -FLT_MAX;
            const float mn = fmaxf(wm, v);
            const float cc = __expf(wm - mn);
            const float e  = __expf(v - mn);
            wm = mn;
            wz = wz * cc + e;
            acc.x = fmaf(acc.x, cc, e * t.x);
            acc.y = fmaf(acc.y, cc, e * t.y);
            acc.z = fmaf(acc.z, cc, e * t.z);
            acc.w = fmaf(acc.w, cc, e * t.w);
        }
        ((float4*)s_part[wid])[lane] = acc;
        if (lane == 0) { s_mw[wid] = wm; s_zw[wid] = wz; }
    }
    __syncthreads();

    // ---- cross-warp combine with max-correction; normalize once ----
    if (tid < 256) {
        const int sR = tid >> 7;
        const int t  = tid & (ED - 1);
        float M = -FLT_MAX;
        #pragma unroll
        for (int w = 0; w < 8; ++w) M = fmaxf(M, s_mw[sR * 8 + w]);
        float sum = 0.f, Z = 0.f;
        #pragma unroll
        for (int w = 0; w < 8; ++w) {
            const float sc = __expf(s_mw[sR * 8 + w] - M);
            sum = fmaf(sc, s_part[sR * 8 + w][t], sum);
            Z   = fmaf(sc, s_zw[sR * 8 + w], Z);
        }
        s_agg[sR][t] = sum * (1.f / Z);
    }
    __syncthreads();

    // ---- h = relu(agg.W_tail^T + head.W_head^T) for BOTH sides ----
    {
        const float4 aL = ((const float4*)s_agg[0])[lane];
        const float4 hL = ((const float4*)s_head[0])[lane];
        const float4 aR = ((const float4*)s_agg[1])[lane];
        const float4 hR = ((const float4*)s_head[1])[lane];
        #pragma unroll 1
        for (int i0 = wid; i0 < ED; i0 += 32) {
            const int i1 = i0 + 16;
            float4 wt0 = ((const float4*)(W_tail + i0 * ED))[lane];
            float4 wh0 = ((const float4*)(W_head + i0 * ED))[lane];
            float4 wt1 = ((const float4*)(W_tail + i1 * ED))[lane];
            float4 wh1 = ((const float4*)(W_head + i1 * ED))[lane];
            float vL0 = aL.x * wt0.x + aL.y * wt0.y + aL.z * wt0.z + aL.w * wt0.w
                      + hL.x * wh0.x + hL.y * wh0.y + hL.z * wh0.z + hL.w * wh0.w;
            float vR0 = aR.x * wt0.x + aR.y * wt0.y + aR.z * wt0.z + aR.w * wt0.w
                      + hR.x * wh0.x + hR.y * wh0.y + hR.z * wh0.z + hR.w * wh0.w;
            float vL1 = aL.x * wt1.x + aL.y * wt1.y + aL.z * wt1.z + aL.w * wt1.w
                      + hL.x * wh1.x + hL.y * wh1.y + hL.z * wh1.z + hL.w * wh1.w;
            float vR1 = aR.x * wt1.x + aR.y * wt1.y + aR.z * wt1.z + aR.w * wt1.w
                      + hR.x * wh1.x + hR.y * wh1.y + hR.z * wh1.z + hR.w * wh1.w;
            #pragma unroll
            for (int d = 16; d >= 1; d >>= 1) {
                vL0 += __shfl_xor_sync(FULLM, vL0, d);
                vR0 += __shfl_xor_sync(FULLM, vR0, d);
                vL1 += __shfl_xor_sync(FULLM, vL1, d);
                vR1 += __shfl_xor_sync(FULLM, vR1, d);
            }
            if (lane == 0) {
                s_x[0][i0] = fmaxf(vL0, 0.f) + s_head[0][i0];
                s_x[1][i0] = fmaxf(vR0, 0.f) + s_head[1][i0];
                s_x[0][i1] = fmaxf(vL1, 0.f) + s_head[0][i1];
                s_x[1][i1] = fmaxf(vR1, 0.f) + s_head[1][i1];
            }
        }
    }
    __syncthreads();

    // ---- two LayerNorms in parallel ----
    if (tid < 256) {
        const int sL = tid >> 7;
        const int t  = tid & (ED - 1);
        const int w4 = t >> 5;
        float xv = s_x[sL][t];
        float s1 = xv, s2 = xv * xv;
        #pragma unroll
        for (int d = 16; d >= 1; d >>= 1) {
            s1 += __shfl_xor_sync(FULLM, s1, d);
            s2 += __shfl_xor_sync(FULLM, s2, d);
        }
        if (lane == 0) { s_redA[sL * 8 + w4] = s1; s_redB[sL * 8 + w4] = s2; }
    }
    __syncthreads();
    if (tid < 256) {
        const int sL = tid >> 7;
        const int t  = tid & (ED - 1);
        if (t == 0) {
            float t1 = 0.f, t2 = 0.f;
            #pragma unroll
            for (int w = 0; w < 4; ++w) { t1 += s_redA[sL * 8 + w]; t2 += s_redB[sL * 8 + w]; }
            float mu  = t1 * (1.f / ED);
            float var = t2 * (1.f / ED) - mu * mu;
            s_stat[sL][0] = mu;
            s_stat[sL][1] = rsqrtf(var + LN_EPS);
        }
    }
    __syncthreads();
    if (tid < 256) {
        const int sL = tid >> 7;
        const int t  = tid & (ED - 1);
        float mu = s_stat[sL][0], rstd = s_stat[sL][1];
        float o = (s_x[sL][t] - mu) * rstd * gamma[t] + beta[t];
        out[((long)sL * BATCH + b) * ED + t] = o;
    }
}

extern "C" void kernel_launch(void* const* d_in, const int* in_sizes, int n_in,
                              void* d_out, int out_size) {
    (void)in_sizes; (void)n_in; (void)out_size;
    const int*   entity     = (const int*)  d_in[0];
    const int*   conn_left  = (const int*)  d_in[1];
    const int*   conn_right = (const int*)  d_in[2];
    const float* emb        = (const float*)d_in[3];
    const float* W_bil      = (const float*)d_in[4];
    const float* W_tail     = (const float*)d_in[5];
    const float* W_head     = (const float*)d_in[6];
    const float* gamma      = (const float*)d_in[7];
    const float* beta       = (const float*)d_in[8];
    float* out = (float*)d_out;

    entity_encoder_kernel<<<BATCH, 512>>>(entity, conn_left, conn_right, emb,
                                          W_bil, W_tail, W_head, gamma, beta, out);
}